// round 8
// baseline (speedup 1.0000x reference)
#include <cuda_runtime.h>
#include <cstdint>

// SpatialPool: fm [B=16, C=512, H=38, W=38] f32 (NCHW)
//   -> out [B, H*W, 9*C] f32, out[b, h*W+w, (di*3+dj)*C + c]
//      = fm[b, c, clamp(h+di-1), clamp(w+dj-1)]  (replicate pad)
//
// R8: R7 load phase (coalesced cp.async into float4-XOR-swizzled smem),
// write phase deduplicated: warp owns a smem position, reads its 128
// channels ONCE (one conflict-free LDS.128), and fans out to every output
// chunk that consumes it (up to 9 predicated, coalesced 512B STG.128.cs).
// Cuts L1 LDS traffic ~4x; every chunk written exactly once.

namespace {
constexpr int HH   = 38;
constexpr int C    = 512;
constexpr int CSUB = 128;        // channels per CTA
constexpr int NCG  = C / CSUB;   // 4
constexpr int NB   = 9;
constexpr int WT   = 19;         // w positions per CTA
constexpr int LW   = WT + 2;     // 21 local cols incl. halo
constexpr int NY   = 2;          // output rows per CTA
constexpr int NR   = NY + 2;     // 4 loaded rows incl. halo
constexpr int NPOS = NR * LW;    // 84 smem positions
constexpr int THREADS = 512;
constexpr int HW   = HH * HH;    // 1444
constexpr int RS4  = NB * C / 4; // 1152 float4 per (b,y,w)
constexpr int YS4  = HH * RS4;   // float4 stride for y+1
}

__device__ __forceinline__ void cp_async4(float* smem_dst, const float* gsrc) {
    uint32_t sa = (uint32_t)__cvta_generic_to_shared(smem_dst);
    asm volatile("cp.async.ca.shared.global [%0], [%1], 4;\n"
                 :: "r"(sa), "l"(gsrc) : "memory");
}

__global__ __launch_bounds__(THREADS, 4)
void spatialpool_kernel(const float* __restrict__ fm, float* __restrict__ out) {
    // logical (pos, c) at smP[pos*128 + 4*((c>>2)^(pos&31)) + (c&3)]
    __shared__ float smP[NPOS * CSUB];   // 43,008 B

    const int lane = threadIdx.x & 31;
    const int wid  = threadIdx.x >> 5;

    const int wh = blockIdx.x & 1;
    const int cg = blockIdx.x >> 1;        // channel group 0..3
    const int w0 = wh * WT;
    const int y0 = blockIdx.y * NY;        // first output row
    const int b  = blockIdx.z;

    const float* __restrict__ fb =
        fm + ((size_t)b * C + (size_t)cg * CSUB) * HW;

    // ---- Load: thread owns p = lane + 32k (k<3), sweeps c = wid + 16m.
    // Offset computed once per p; channel stride is a compile-time
    // immediate. Lanes sweep consecutive p -> coalesced cp.async. ----
    {
        const float* __restrict__ fc = fb + (size_t)wid * HW;  // c0 = wid
        const int c3  = wid & 3;
        const int cq0 = wid >> 2;
        #pragma unroll
        for (int k = 0; k < 3; ++k) {
            int p = lane + 32 * k;
            if (k == 2 && p >= NPOS) break;
            int r  = p / LW;
            int l  = p - r * LW;
            int yl = min(max(y0 - 1 + r, 0), HH - 1);
            int xg = min(max(w0 - 1 + l, 0), HH - 1);
            const float* __restrict__ g = fc + yl * HH + xg;
            const int swk = (p << 7) + c3;
            #pragma unroll
            for (int m = 0; m < 8; ++m) {
                int sw = swk + (((cq0 + 4 * m) ^ lane) << 2);
                cp_async4(&smP[sw], g + m * 16 * HW);
            }
        }
    }
    asm volatile("cp.async.wait_all;\n" ::: "memory");
    __syncthreads();

    // ---- Write: warp-per-POSITION. One conflict-free LDS.128, then
    // predicated fan-out to all chunks consuming this position. Each of
    // the 342 chunks is produced by exactly one (pos, di, dj). ----
    float4* __restrict__ out4 = (float4*)out;
    const size_t rowbase =
        ((size_t)b * HW + (size_t)y0 * HH + w0) * (size_t)RS4
        + (size_t)cg * (CSUB / 4) + lane;

    for (int pp = wid; pp < NPOS; pp += THREADS / 32) {
        const int r = pp / LW;          // loaded row 0..3
        const int l = pp - r * LW;      // local col 0..20

        const float4 v = *(const float4*)
            &smP[(pp << 7) + ((lane ^ (pp & 31)) << 2)];

        const size_t pbase = rowbase + (size_t)l * RS4;   // dj=0 col base

        #pragma unroll
        for (int di = 0; di < 3; ++di) {
            const int o = r - di;                // output row within pair
            if (o < 0 || o >= NY) continue;      // runtime predicate
            const size_t obase = pbase + (size_t)o * YS4;
            #pragma unroll
            for (int dj = 0; dj < 3; ++dj) {
                const int wl = l - dj;
                if (wl < 0 || wl >= WT) continue;
                // addr = obase - dj*RS4 + n*(C/4), n = di*3+dj (all imm)
                __stcs(&out4[obase - (size_t)dj * RS4
                             + (di * 3 + dj) * (C / 4)], v);
            }
        }
    }
}

extern "C" void kernel_launch(void* const* d_in, const int* in_sizes, int n_in,
                              void* d_out, int out_size) {
    const float* fm = (const float*)d_in[0];
    float* out = (float*)d_out;
    (void)in_sizes; (void)n_in; (void)out_size;

    dim3 grid(2 * NCG, HH / NY, 16);   // (8, 19, 16) = 2432 CTAs
    spatialpool_kernel<<<grid, THREADS>>>(fm, out);
}